// round 10
// baseline (speedup 1.0000x reference)
#include <cuda_runtime.h>
#include <cstdint>
#include <cstddef>

// ---------------- JAX threefry derivation (partitionable) ----------------
// R6: (outer-key direct, e=2t+1)  -> rel_err 0.4302  WRONG
// R8: (outer-key direct, e=M+t)   -> rel_err 0.4314  WRONG
// R9 finding (from jax/_src/random.py::_randint source): randint performs an
// INNER split of its key: k1,k2 = split(key); lower_bits = random_bits(k2).
// span=128 is a power of two -> multiplier = (2^16 % 128)^2 % 128 = 0, so
// col = lower_bits % 128, with lower_bits keyed by INNER child 1.
// Chain: key(42)=(0,42); outer split -> K1=tf(key,0,0), K2=tf(key,0,1);
// inner split of each -> lower key L = tf(K,0,1);
// bits[t] = o0^o1 of tf(L, 0, t); col = bits & 127.
// LOWER_FROM_CHILD0: fallback if higher/lower child order is reversed.
// (R9 submission never ran: infra timeout. R10 = identical resubmission.)
#define LOWER_FROM_CHILD0 0

static constexpr int F    = 256;   // feature dim
static constexpr int H2   = 256;   // 2*H concat dim
static constexpr int DEG  = 128;   // MAX_DEG
static constexpr int B    = 512;   // batch
static constexpr int S1n  = 25;
static constexpr int S2n  = 10;
static constexpr int NS1  = B * S2n;       // 5120 first-hop samples
static constexpr int MROWS = B + NS1;      // 5632 rows through layer 0

// scratch (static device allocation: allowed)
__device__ int   g_s1[NS1];
__device__ float g_xneigh[(size_t)MROWS * F];
__device__ float g_H[(size_t)MROWS * H2];

// ---------------- threefry2x32 (jax rotation schedule) ----------------
__device__ __forceinline__ uint32_t rotl32(uint32_t x, int r) {
    return (x << r) | (x >> (32 - r));
}

__device__ __forceinline__ void tf2x32(uint32_t k0, uint32_t k1,
                                       uint32_t x0, uint32_t x1,
                                       uint32_t& o0, uint32_t& o1) {
    uint32_t ks2 = k0 ^ k1 ^ 0x1BD11BDAu;
    x0 += k0; x1 += k1;
#define TFR(r) { x0 += x1; x1 = rotl32(x1, r); x1 ^= x0; }
    TFR(13) TFR(15) TFR(26) TFR(6)
    x0 += k1;  x1 += ks2 + 1u;
    TFR(17) TFR(29) TFR(16) TFR(24)
    x0 += ks2; x1 += k0 + 2u;
    TFR(13) TFR(15) TFR(26) TFR(6)
    x0 += k0;  x1 += k1 + 3u;
    TFR(17) TFR(29) TFR(16) TFR(24)
    x0 += k1;  x1 += ks2 + 4u;
    TFR(13) TFR(15) TFR(26) TFR(6)
    x0 += ks2; x1 += k0 + 5u;
#undef TFR
    o0 = x0; o1 = x1;
}

// Derive the two randint lower-bit keys L1 (hop-1) and L2 (hop-2).
__device__ __forceinline__ void get_lower_keys(uint32_t& l1a, uint32_t& l1b,
                                               uint32_t& l2a, uint32_t& l2b) {
#if LOWER_FROM_CHILD0
    const uint32_t inner = 0u;
#else
    const uint32_t inner = 1u;   // k1,k2 = split(key); lower_bits from k2 = child 1
#endif
    uint32_t k1a, k1b, k2a, k2b;
    tf2x32(0u, 42u, 0u, 0u, k1a, k1b);        // outer split child 0 -> hop-1 key
    tf2x32(0u, 42u, 0u, 1u, k2a, k2b);        // outer split child 1 -> hop-2 key
    tf2x32(k1a, k1b, 0u, inner, l1a, l1b);    // randint inner split -> lower key
    tf2x32(k2a, k2b, 0u, inner, l2a, l2b);
}

// col index for flat sample t under lower key (la, lb):
// random_bits(L)[t] & 127, bits[t] = o0 ^ o1 of tf(L, (0, t))
__device__ __forceinline__ uint32_t sample_col(uint32_t la, uint32_t lb,
                                               uint32_t t) {
    uint32_t o0, o1;
    tf2x32(la, lb, 0u, t, o0, o1);
    return (o0 ^ o1) & (DEG - 1u);
}

// first-hop sample t (0..NS1-1): adj[batch[t/10], c1(t)]
__device__ __forceinline__ int first_hop(const int* __restrict__ adj,
                                         const int* __restrict__ batch,
                                         uint32_t l1a, uint32_t l1b, int t) {
    uint32_t c = sample_col(l1a, l1b, (uint32_t)t);
    return adj[(size_t)batch[t / S2n] * DEG + c];
}

// ---------------- K2: sampling + neighbor means ----------------
// block b < 512:  xneigh[b] = mean_{j<10} features[s1(b*10+j)]  (s1 recomputed)
// block b >= 512: p=b-512:  sp = s1(p) computed inline, g_s1[p] = sp (for K3),
//                 xneigh[b] = mean_{q<25} features[adj[sp, c2(p*25+q)]]
__global__ __launch_bounds__(256) void k_means(const float* __restrict__ features,
                                               const int* __restrict__ adj,
                                               const int* __restrict__ batch) {
    __shared__ int nodes[S1n];
    int b   = blockIdx.x;
    int tid = threadIdx.x;

    uint32_t l1a, l1b, l2a, l2b;
    get_lower_keys(l1a, l1b, l2a, l2b);

    if (b < B) {
        if (tid < S2n)
            nodes[tid] = first_hop(adj, batch, l1a, l1b, b * S2n + tid);
        __syncthreads();
        // 10 gathers: 2 independent chains of 5 for MLP
        float s0 = 0.f, s1 = 0.f;
#pragma unroll
        for (int j = 0; j < S2n; j += 2) {
            s0 += features[(size_t)nodes[j]     * F + tid];
            s1 += features[(size_t)nodes[j + 1] * F + tid];
        }
        g_xneigh[(size_t)b * F + tid] = (s0 + s1) * (1.f / (float)S2n);
    } else {
        int p = b - B;
        __shared__ int sp_sh;
        if (tid == 0) {
            int sp = first_hop(adj, batch, l1a, l1b, p);
            g_s1[p] = sp;           // consumed by K3 (next kernel)
            sp_sh = sp;
        }
        __syncthreads();
        if (tid < S1n) {
            uint32_t c = sample_col(l2a, l2b, (uint32_t)(p * S1n + tid));
            nodes[tid] = adj[(size_t)sp_sh * DEG + c];
        }
        __syncthreads();
        // 25 gathers: 5 independent accumulator chains -> MLP ~5
        float s0 = 0.f, s1 = 0.f, s2 = 0.f, s3 = 0.f, s4 = 0.f;
#pragma unroll
        for (int j = 0; j < S1n; j += 5) {
            s0 += features[(size_t)nodes[j]     * F + tid];
            s1 += features[(size_t)nodes[j + 1] * F + tid];
            s2 += features[(size_t)nodes[j + 2] * F + tid];
            s3 += features[(size_t)nodes[j + 3] * F + tid];
            s4 += features[(size_t)nodes[j + 4] * F + tid];
        }
        g_xneigh[(size_t)b * F + tid] =
            (((s0 + s1) + (s2 + s3)) + s4) * (1.f / (float)S1n);
    }
}

// ---------------- K3: layer-0 dual GEMM + relu ----------------
// H[r, 0:128]   = relu( X_self[r]  @ W_self_0 ),  X_self[r]  = features[idx(r)]
// H[r, 128:256] = relu( X_neigh[r] @ W_neigh_0 ), X_neigh[r] = g_xneigh[r]
// Tiles: 128(M) x 64(N), K-chunk 16, 256 threads, 8x4 microtile.
// grid = (44, 4): blockIdx.y 0,1 -> self half; 2,3 -> neigh half.
__global__ __launch_bounds__(256) void k_gemm0(const float* __restrict__ features,
                                               const int* __restrict__ batch,
                                               const float* __restrict__ Ws0,
                                               const float* __restrict__ Wn0) {
    __shared__ float As[16][132];   // k-major, padded
    __shared__ float Bs[16][68];

    const int tid = threadIdx.x;
    const int r0  = blockIdx.x * 128;
    const int yb  = blockIdx.y;
    const bool selfhalf = (yb < 2);
    const int ncol0 = (yb & 1) * 64;
    const float* __restrict__ W = selfhalf ? Ws0 : Wn0;

    // A staging map: float4 chunks i = tid and tid+256; row = i/4, kq = i%4
    const int rowA1 = tid >> 2;        // 0..63
    const int rowA2 = 64 + rowA1;
    const int kq    = tid & 3;

    const float* aptr1;
    const float* aptr2;
    {
        int ra = r0 + rowA1, rb = r0 + rowA2;
        if (selfhalf) {
            int na = (ra < B) ? batch[ra] : g_s1[ra - B];
            int nb = (rb < B) ? batch[rb] : g_s1[rb - B];
            aptr1 = features + (size_t)na * F;
            aptr2 = features + (size_t)nb * F;
        } else {
            aptr1 = g_xneigh + (size_t)ra * F;
            aptr2 = g_xneigh + (size_t)rb * F;
        }
    }

    // B staging map
    const int bk = tid >> 4;           // 0..15
    const int bn = (tid & 15) * 4;     // 0..60

    const int tx = tid & 15, ty = tid >> 4;
    const int mfrag = ty * 8;
    const int nfrag = tx * 4;

    float acc[8][4];
#pragma unroll
    for (int i = 0; i < 8; i++)
#pragma unroll
        for (int j = 0; j < 4; j++) acc[i][j] = 0.f;

    for (int kk = 0; kk < F; kk += 16) {
        float4 a1 = *reinterpret_cast<const float4*>(aptr1 + kk + kq * 4);
        float4 a2 = *reinterpret_cast<const float4*>(aptr2 + kk + kq * 4);
        float4 bv = *reinterpret_cast<const float4*>(W + (size_t)(kk + bk) * 128 + ncol0 + bn);
        __syncthreads();
        As[kq * 4 + 0][rowA1] = a1.x; As[kq * 4 + 1][rowA1] = a1.y;
        As[kq * 4 + 2][rowA1] = a1.z; As[kq * 4 + 3][rowA1] = a1.w;
        As[kq * 4 + 0][rowA2] = a2.x; As[kq * 4 + 1][rowA2] = a2.y;
        As[kq * 4 + 2][rowA2] = a2.z; As[kq * 4 + 3][rowA2] = a2.w;
        *reinterpret_cast<float4*>(&Bs[bk][bn]) = bv;
        __syncthreads();
#pragma unroll
        for (int k = 0; k < 16; k++) {
            float4 b4 = *reinterpret_cast<const float4*>(&Bs[k][nfrag]);
            float4 a0 = *reinterpret_cast<const float4*>(&As[k][mfrag]);
            float4 ah = *reinterpret_cast<const float4*>(&As[k][mfrag + 4]);
            float av[8] = {a0.x, a0.y, a0.z, a0.w, ah.x, ah.y, ah.z, ah.w};
            float bvv[4] = {b4.x, b4.y, b4.z, b4.w};
#pragma unroll
            for (int i = 0; i < 8; i++)
#pragma unroll
                for (int j = 0; j < 4; j++)
                    acc[i][j] += av[i] * bvv[j];
        }
    }

    const int gcol = (selfhalf ? 0 : 128) + ncol0 + nfrag;
#pragma unroll
    for (int i = 0; i < 8; i++) {
        float4 v;
        v.x = fmaxf(acc[i][0], 0.f);
        v.y = fmaxf(acc[i][1], 0.f);
        v.z = fmaxf(acc[i][2], 0.f);
        v.w = fmaxf(acc[i][3], 0.f);
        *reinterpret_cast<float4*>(&g_H[(size_t)(r0 + mfrag + i) * H2 + gcol]) = v;
    }
}

// ---------------- K4: layer-1 GEMM + l2 normalize ----------------
// 8 output rows per block; 256 threads = 256 output columns.
__global__ __launch_bounds__(256) void k_layer1(const float* __restrict__ Ws1,
                                                const float* __restrict__ Wn1,
                                                float* __restrict__ out) {
    __shared__ float xs[2][8][H2];   // [0]=self rows, [1]=neighbor means
    __shared__ float rowsq[8];
    const int tid = threadIdx.x;
    const int r0  = blockIdx.x * 8;

#pragma unroll
    for (int i = 0; i < 8; i++)
        xs[0][i][tid] = g_H[(size_t)(r0 + i) * H2 + tid];
#pragma unroll
    for (int i = 0; i < 8; i++) {
        float s0 = 0.f, s1 = 0.f;
#pragma unroll
        for (int j = 0; j < S2n; j += 2) {
            s0 += g_H[(size_t)(B + (r0 + i) * S2n + j)     * H2 + tid];
            s1 += g_H[(size_t)(B + (r0 + i) * S2n + j + 1) * H2 + tid];
        }
        xs[1][i][tid] = (s0 + s1) * (1.f / (float)S2n);
    }
    if (tid < 8) rowsq[tid] = 0.f;
    __syncthreads();

    const bool sp = (tid < 128);
    const float* __restrict__ W = sp ? (Ws1 + tid) : (Wn1 + (tid - 128));
    const float* X = sp ? &xs[0][0][0] : &xs[1][0][0];

    float acc[8] = {0.f, 0.f, 0.f, 0.f, 0.f, 0.f, 0.f, 0.f};
#pragma unroll 8
    for (int k = 0; k < H2; k++) {
        float wv = W[(size_t)k * 128];
#pragma unroll
        for (int i = 0; i < 8; i++)
            acc[i] += X[i * H2 + k] * wv;
    }

#pragma unroll
    for (int i = 0; i < 8; i++) {
        float v = acc[i] * acc[i];
#pragma unroll
        for (int o = 16; o > 0; o >>= 1)
            v += __shfl_down_sync(0xffffffffu, v, o);
        if ((tid & 31) == 0) atomicAdd(&rowsq[i], v);
    }
    __syncthreads();

#pragma unroll
    for (int i = 0; i < 8; i++) {
        float nrm = fmaxf(sqrtf(rowsq[i]), 1e-12f);
        out[(size_t)(r0 + i) * H2 + tid] = acc[i] / nrm;
    }
}

// ---------------- launch ----------------
extern "C" void kernel_launch(void* const* d_in, const int* in_sizes, int n_in,
                              void* d_out, int out_size) {
    const float* features = (const float*)d_in[0];
    const int*   adj      = (const int*)d_in[1];
    const int*   batch    = (const int*)d_in[2];
    const float* Ws0      = (const float*)d_in[3];
    const float* Wn0      = (const float*)d_in[4];
    const float* Ws1      = (const float*)d_in[5];
    const float* Wn1      = (const float*)d_in[6];
    float* out = (float*)d_out;

    k_means<<<MROWS, 256>>>(features, adj, batch);
    k_gemm0<<<dim3(44, 4), 256>>>(features, batch, Ws0, Wn0);
    k_layer1<<<B / 8, 256>>>(Ws1, Wn1, out);
}

// round 15
// speedup vs baseline: 1.1108x; 1.1108x over previous
#include <cuda_runtime.h>
#include <cstdint>
#include <cstddef>

// ---------------- JAX threefry derivation (partitionable, VERIFIED R10) ------
// key(42)=(0,42); outer split -> K1=tf(key,0,0), K2=tf(key,0,1);
// _randint inner split -> lower key L = tf(K,0,1);
// bits[t] = o0^o1 of tf(L, 0, t); col = bits & 127.
// R10: rel_err 1.56e-7 PASS, dur_us 88.5 (k_means 24.4us, DRAM 40.7%, issue 35.9%).
// R11-R15 experiment: float4 k_means (4 rows/block) + double-buffered k_gemm0.
// (R11-R14 never ran: infra timeouts. R15 = identical resubmission.)

static constexpr int F    = 256;   // feature dim
static constexpr int H2   = 256;   // 2*H concat dim
static constexpr int DEG  = 128;   // MAX_DEG
static constexpr int B    = 512;   // batch
static constexpr int S1n  = 25;
static constexpr int S2n  = 10;
static constexpr int NS1  = B * S2n;       // 5120 first-hop samples
static constexpr int MROWS = B + NS1;      // 5632 rows through layer 0

// scratch (static device allocation: allowed)
__device__ int   g_s1[NS1];
__device__ float g_xneigh[(size_t)MROWS * F];
__device__ float g_H[(size_t)MROWS * H2];

// ---------------- threefry2x32 (jax rotation schedule) ----------------
__device__ __forceinline__ uint32_t rotl32(uint32_t x, int r) {
    return (x << r) | (x >> (32 - r));
}

__device__ __forceinline__ void tf2x32(uint32_t k0, uint32_t k1,
                                       uint32_t x0, uint32_t x1,
                                       uint32_t& o0, uint32_t& o1) {
    uint32_t ks2 = k0 ^ k1 ^ 0x1BD11BDAu;
    x0 += k0; x1 += k1;
#define TFR(r) { x0 += x1; x1 = rotl32(x1, r); x1 ^= x0; }
    TFR(13) TFR(15) TFR(26) TFR(6)
    x0 += k1;  x1 += ks2 + 1u;
    TFR(17) TFR(29) TFR(16) TFR(24)
    x0 += ks2; x1 += k0 + 2u;
    TFR(13) TFR(15) TFR(26) TFR(6)
    x0 += k0;  x1 += k1 + 3u;
    TFR(17) TFR(29) TFR(16) TFR(24)
    x0 += k1;  x1 += ks2 + 4u;
    TFR(13) TFR(15) TFR(26) TFR(6)
    x0 += ks2; x1 += k0 + 5u;
#undef TFR
    o0 = x0; o1 = x1;
}

// Derive the two randint lower-bit keys L1 (hop-1) and L2 (hop-2).
__device__ __forceinline__ void get_lower_keys(uint32_t& l1a, uint32_t& l1b,
                                               uint32_t& l2a, uint32_t& l2b) {
    uint32_t k1a, k1b, k2a, k2b;
    tf2x32(0u, 42u, 0u, 0u, k1a, k1b);        // outer split child 0 -> hop-1 key
    tf2x32(0u, 42u, 0u, 1u, k2a, k2b);        // outer split child 1 -> hop-2 key
    tf2x32(k1a, k1b, 0u, 1u, l1a, l1b);       // randint inner split child 1
    tf2x32(k2a, k2b, 0u, 1u, l2a, l2b);
}

__device__ __forceinline__ uint32_t sample_col(uint32_t la, uint32_t lb,
                                               uint32_t t) {
    uint32_t o0, o1;
    tf2x32(la, lb, 0u, t, o0, o1);
    return (o0 ^ o1) & (DEG - 1u);
}

// first-hop sample t (0..NS1-1): adj[batch[t/10], c1(t)]
__device__ __forceinline__ int first_hop(const int* __restrict__ adj,
                                         const int* __restrict__ batch,
                                         uint32_t l1a, uint32_t l1b, int t) {
    uint32_t c = sample_col(l1a, l1b, (uint32_t)t);
    return adj[(size_t)batch[t / S2n] * DEG + c];
}

__device__ __forceinline__ float4 f4add(float4 a, float4 b) {
    return make_float4(a.x + b.x, a.y + b.y, a.z + b.z, a.w + b.w);
}

// ---------------- K2 v2: sampling + neighbor means (float4, 4 rows/block) ----
// 1408 blocks x 256 threads; group g = tid/64 handles one output row,
// lane = tid%64 covers F=256 via float4.
// blocks [0,128):    self rows   b = blk*4+g      (mean of 10 hop-1 features)
// blocks [128,1408): neigh rows  p = (blk-128)*4+g (mean of 25 hop-2 features;
//                    also writes g_s1[p] for K3)
static constexpr int NB_SELF = B / 4;              // 128
static constexpr int NB_MEANS = NB_SELF + NS1 / 4; // 1408

__global__ __launch_bounds__(256) void k_means(const float* __restrict__ features,
                                               const int* __restrict__ adj,
                                               const int* __restrict__ batch) {
    __shared__ int nodes[4][S1n];
    __shared__ int sps[4];
    const int tid  = threadIdx.x;
    const int g    = tid >> 6;
    const int lane = tid & 63;
    const int blk  = blockIdx.x;

    uint32_t l1a, l1b, l2a, l2b;
    get_lower_keys(l1a, l1b, l2a, l2b);

    if (blk < NB_SELF) {
        const int b = blk * 4 + g;
        if (lane < S2n)
            nodes[g][lane] = first_hop(adj, batch, l1a, l1b, b * S2n + lane);
        __syncthreads();
        float4 s0 = make_float4(0.f, 0.f, 0.f, 0.f), s1 = s0;
#pragma unroll
        for (int j = 0; j < S2n; j += 2) {
            s0 = f4add(s0, *reinterpret_cast<const float4*>(
                               features + (size_t)nodes[g][j] * F + lane * 4));
            s1 = f4add(s1, *reinterpret_cast<const float4*>(
                               features + (size_t)nodes[g][j + 1] * F + lane * 4));
        }
        float4 r = f4add(s0, s1);
        const float inv = 1.f / (float)S2n;
        *reinterpret_cast<float4*>(g_xneigh + (size_t)b * F + lane * 4) =
            make_float4(r.x * inv, r.y * inv, r.z * inv, r.w * inv);
    } else {
        const int p = (blk - NB_SELF) * 4 + g;
        if (lane == 0) {
            int sp = first_hop(adj, batch, l1a, l1b, p);
            g_s1[p] = sp;           // consumed by K3 (next kernel)
            sps[g] = sp;
        }
        __syncthreads();
        if (lane < S1n) {
            uint32_t c = sample_col(l2a, l2b, (uint32_t)(p * S1n + lane));
            nodes[g][lane] = adj[(size_t)sps[g] * DEG + c];
        }
        __syncthreads();
        float4 s0 = make_float4(0.f, 0.f, 0.f, 0.f);
        float4 s1 = s0, s2 = s0, s3 = s0, s4 = s0;
#pragma unroll
        for (int j = 0; j < S1n; j += 5) {
            s0 = f4add(s0, *reinterpret_cast<const float4*>(
                               features + (size_t)nodes[g][j]     * F + lane * 4));
            s1 = f4add(s1, *reinterpret_cast<const float4*>(
                               features + (size_t)nodes[g][j + 1] * F + lane * 4));
            s2 = f4add(s2, *reinterpret_cast<const float4*>(
                               features + (size_t)nodes[g][j + 2] * F + lane * 4));
            s3 = f4add(s3, *reinterpret_cast<const float4*>(
                               features + (size_t)nodes[g][j + 3] * F + lane * 4));
            s4 = f4add(s4, *reinterpret_cast<const float4*>(
                               features + (size_t)nodes[g][j + 4] * F + lane * 4));
        }
        float4 r = f4add(f4add(f4add(s0, s1), f4add(s2, s3)), s4);
        const float inv = 1.f / (float)S1n;
        *reinterpret_cast<float4*>(g_xneigh + (size_t)(B + p) * F + lane * 4) =
            make_float4(r.x * inv, r.y * inv, r.z * inv, r.w * inv);
    }
}

// ---------------- K3 v2: layer-0 dual GEMM + relu, double-buffered ----------
// H[r, 0:128]   = relu( X_self[r]  @ W_self_0 ),  X_self[r]  = features[idx(r)]
// H[r, 128:256] = relu( X_neigh[r] @ W_neigh_0 ), X_neigh[r] = g_xneigh[r]
// Tiles: 128(M) x 64(N), K-chunk 16, 256 threads, 8x4 microtile.
// Double-buffered smem: gmem prefetch overlaps the 512-FMA compute phase;
// one __syncthreads per chunk.
__global__ __launch_bounds__(256) void k_gemm0(const float* __restrict__ features,
                                               const int* __restrict__ batch,
                                               const float* __restrict__ Ws0,
                                               const float* __restrict__ Wn0) {
    __shared__ float As[2][16][132];   // k-major, padded
    __shared__ float Bs[2][16][68];

    const int tid = threadIdx.x;
    const int r0  = blockIdx.x * 128;
    const int yb  = blockIdx.y;
    const bool selfhalf = (yb < 2);
    const int ncol0 = (yb & 1) * 64;
    const float* __restrict__ W = selfhalf ? Ws0 : Wn0;

    // A staging map: float4 chunks i = tid and tid+256; row = i/4, kq = i%4
    const int rowA1 = tid >> 2;        // 0..63
    const int rowA2 = 64 + rowA1;
    const int kq    = tid & 3;

    const float* aptr1;
    const float* aptr2;
    {
        int ra = r0 + rowA1, rb = r0 + rowA2;
        if (selfhalf) {
            int na = (ra < B) ? batch[ra] : g_s1[ra - B];
            int nb = (rb < B) ? batch[rb] : g_s1[rb - B];
            aptr1 = features + (size_t)na * F;
            aptr2 = features + (size_t)nb * F;
        } else {
            aptr1 = g_xneigh + (size_t)ra * F;
            aptr2 = g_xneigh + (size_t)rb * F;
        }
    }

    // B staging map
    const int bk = tid >> 4;           // 0..15
    const int bn = (tid & 15) * 4;     // 0..60

    const int tx = tid & 15, ty = tid >> 4;
    const int mfrag = ty * 8;
    const int nfrag = tx * 4;

    float acc[8][4];
#pragma unroll
    for (int i = 0; i < 8; i++)
#pragma unroll
        for (int j = 0; j < 4; j++) acc[i][j] = 0.f;

    // prologue: load + store chunk 0
    float4 a1 = *reinterpret_cast<const float4*>(aptr1 + kq * 4);
    float4 a2 = *reinterpret_cast<const float4*>(aptr2 + kq * 4);
    float4 bv = *reinterpret_cast<const float4*>(W + (size_t)bk * 128 + ncol0 + bn);
    As[0][kq * 4 + 0][rowA1] = a1.x; As[0][kq * 4 + 1][rowA1] = a1.y;
    As[0][kq * 4 + 2][rowA1] = a1.z; As[0][kq * 4 + 3][rowA1] = a1.w;
    As[0][kq * 4 + 0][rowA2] = a2.x; As[0][kq * 4 + 1][rowA2] = a2.y;
    As[0][kq * 4 + 2][rowA2] = a2.z; As[0][kq * 4 + 3][rowA2] = a2.w;
    *reinterpret_cast<float4*>(&Bs[0][bk][bn]) = bv;
    __syncthreads();

    for (int c = 0; c < 16; c++) {
        const int cur = c & 1;
        if (c < 15) {   // prefetch next chunk (latency hidden under compute)
            const int kk = (c + 1) * 16;
            a1 = *reinterpret_cast<const float4*>(aptr1 + kk + kq * 4);
            a2 = *reinterpret_cast<const float4*>(aptr2 + kk + kq * 4);
            bv = *reinterpret_cast<const float4*>(W + (size_t)(kk + bk) * 128 + ncol0 + bn);
        }
        const float (*Ac)[132] = As[cur];
        const float (*Bc)[68]  = Bs[cur];
#pragma unroll
        for (int k = 0; k < 16; k++) {
            float4 b4 = *reinterpret_cast<const float4*>(&Bc[k][nfrag]);
            float4 a0 = *reinterpret_cast<const float4*>(&Ac[k][mfrag]);
            float4 ah = *reinterpret_cast<const float4*>(&Ac[k][mfrag + 4]);
            float av[8] = {a0.x, a0.y, a0.z, a0.w, ah.x, ah.y, ah.z, ah.w};
            float bvv[4] = {b4.x, b4.y, b4.z, b4.w};
#pragma unroll
            for (int i = 0; i < 8; i++)
#pragma unroll
                for (int j = 0; j < 4; j++)
                    acc[i][j] += av[i] * bvv[j];
        }
        if (c < 15) {   // store into the other buffer (read last at chunk c-1)
            const int nxt = cur ^ 1;
            As[nxt][kq * 4 + 0][rowA1] = a1.x; As[nxt][kq * 4 + 1][rowA1] = a1.y;
            As[nxt][kq * 4 + 2][rowA1] = a1.z; As[nxt][kq * 4 + 3][rowA1] = a1.w;
            As[nxt][kq * 4 + 0][rowA2] = a2.x; As[nxt][kq * 4 + 1][rowA2] = a2.y;
            As[nxt][kq * 4 + 2][rowA2] = a2.z; As[nxt][kq * 4 + 3][rowA2] = a2.w;
            *reinterpret_cast<float4*>(&Bs[nxt][bk][bn]) = bv;
            __syncthreads();
        }
    }

    const int gcol = (selfhalf ? 0 : 128) + ncol0 + nfrag;
#pragma unroll
    for (int i = 0; i < 8; i++) {
        float4 v;
        v.x = fmaxf(acc[i][0], 0.f);
        v.y = fmaxf(acc[i][1], 0.f);
        v.z = fmaxf(acc[i][2], 0.f);
        v.w = fmaxf(acc[i][3], 0.f);
        *reinterpret_cast<float4*>(&g_H[(size_t)(r0 + mfrag + i) * H2 + gcol]) = v;
    }
}

// ---------------- K4: layer-1 GEMM + l2 normalize ----------------
// 8 output rows per block; 256 threads = 256 output columns.
__global__ __launch_bounds__(256) void k_layer1(const float* __restrict__ Ws1,
                                                const float* __restrict__ Wn1,
                                                float* __restrict__ out) {
    __shared__ float xs[2][8][H2];   // [0]=self rows, [1]=neighbor means
    __shared__ float rowsq[8];
    const int tid = threadIdx.x;
    const int r0  = blockIdx.x * 8;

#pragma unroll
    for (int i = 0; i < 8; i++)
        xs[0][i][tid] = g_H[(size_t)(r0 + i) * H2 + tid];
#pragma unroll
    for (int i = 0; i < 8; i++) {
        float s0 = 0.f, s1 = 0.f;
#pragma unroll
        for (int j = 0; j < S2n; j += 2) {
            s0 += g_H[(size_t)(B + (r0 + i) * S2n + j)     * H2 + tid];
            s1 += g_H[(size_t)(B + (r0 + i) * S2n + j + 1) * H2 + tid];
        }
        xs[1][i][tid] = (s0 + s1) * (1.f / (float)S2n);
    }
    if (tid < 8) rowsq[tid] = 0.f;
    __syncthreads();

    const bool sp = (tid < 128);
    const float* __restrict__ W = sp ? (Ws1 + tid) : (Wn1 + (tid - 128));
    const float* X = sp ? &xs[0][0][0] : &xs[1][0][0];

    float acc[8] = {0.f, 0.f, 0.f, 0.f, 0.f, 0.f, 0.f, 0.f};
#pragma unroll 8
    for (int k = 0; k < H2; k++) {
        float wv = W[(size_t)k * 128];
#pragma unroll
        for (int i = 0; i < 8; i++)
            acc[i] += X[i * H2 + k] * wv;
    }

#pragma unroll
    for (int i = 0; i < 8; i++) {
        float v = acc[i] * acc[i];
#pragma unroll
        for (int o = 16; o > 0; o >>= 1)
            v += __shfl_down_sync(0xffffffffu, v, o);
        if ((tid & 31) == 0) atomicAdd(&rowsq[i], v);
    }
    __syncthreads();

#pragma unroll
    for (int i = 0; i < 8; i++) {
        float nrm = fmaxf(sqrtf(rowsq[i]), 1e-12f);
        out[(size_t)(r0 + i) * H2 + tid] = acc[i] / nrm;
    }
}

// ---------------- launch ----------------
extern "C" void kernel_launch(void* const* d_in, const int* in_sizes, int n_in,
                              void* d_out, int out_size) {
    const float* features = (const float*)d_in[0];
    const int*   adj      = (const int*)d_in[1];
    const int*   batch    = (const int*)d_in[2];
    const float* Ws0      = (const float*)d_in[3];
    const float* Wn0      = (const float*)d_in[4];
    const float* Ws1      = (const float*)d_in[5];
    const float* Wn1      = (const float*)d_in[6];
    float* out = (float*)d_out;

    k_means<<<NB_MEANS, 256>>>(features, adj, batch);
    k_gemm0<<<dim3(44, 4), 256>>>(features, batch, Ws0, Wn0);
    k_layer1<<<B / 8, 256>>>(Ws1, Wn1, out);
}